// round 14
// baseline (speedup 1.0000x reference)
#include <cuda_runtime.h>
#include <cuda_fp16.h>
#include <math.h>
#include <stdint.h>

#define BDIM   512
#define SDIM   1024
#define BATCH  8
#define NHEADS 8
#define HD     64
#define DFF    2048
#define NTOK   (BATCH * SDIM)   // 8192

// Scratch
__device__ __half g_srch[NTOK * BDIM];
__device__ __half g_q [BATCH * BDIM * SDIM];   // [B,H,S,64], pre-scaled by 1/64
__device__ __half g_k [BATCH * BDIM * SDIM];   // [B,H,S,64]
__device__ __half g_v [BATCH * BDIM * SDIM];   // [B,D,S]
__device__ __half g_av[NTOK * BDIM];
__device__ float  g_t1[NTOK * BDIM];
__device__ __half g_x1[NTOK * BDIM];
__device__ __half g_ff[NTOK * DFF];
__device__ __half g_wt[2 * 3 * BDIM * BDIM];
__device__ __half g_wc[2 * BDIM * BDIM + 2 * DFF * BDIM];

#define WC_WV 0
#define WC_WO (BDIM * BDIM)
#define WC_W1 (2 * BDIM * BDIM)
#define WC_W2 (2 * BDIM * BDIM + DFF * BDIM)

__device__ __forceinline__ uint32_t f2h2(float lo, float hi) {
    __half2 h = __floats2half2_rn(lo, hi);
    return *reinterpret_cast<uint32_t*>(&h);
}

__device__ __forceinline__ void mma_f16(float c[4], const uint32_t a[4], const uint32_t b[2]) {
    asm volatile(
        "mma.sync.aligned.m16n8k16.row.col.f32.f16.f16.f32 "
        "{%0,%1,%2,%3}, {%4,%5,%6,%7}, {%8,%9}, {%0,%1,%2,%3};"
        : "+f"(c[0]), "+f"(c[1]), "+f"(c[2]), "+f"(c[3])
        : "r"(a[0]), "r"(a[1]), "r"(a[2]), "r"(a[3]), "r"(b[0]), "r"(b[1]));
}

__device__ __forceinline__ uint32_t smem_u32(const void* p) {
    uint32_t a;
    asm("{ .reg .u64 t; cvta.to.shared.u64 t, %1; cvt.u32.u64 %0, t; }" : "=r"(a) : "l"(p));
    return a;
}

#define CP16(dst, src) \
    asm volatile("cp.async.cg.shared.global [%0], [%1], 16;" :: "r"(dst), "l"(src))
#define CP16Z(dst, src, sz) \
    asm volatile("cp.async.cg.shared.global [%0], [%1], 16, %2;" :: "r"(dst), "l"(src), "r"(sz))
#define CP_COMMIT() asm volatile("cp.async.commit_group;")
#define CP_WAIT1()  asm volatile("cp.async.wait_group 1;")
#define CP_WAIT0()  asm volatile("cp.async.wait_group 0;")

#define LDSM_X4(R, ADDR) \
    asm volatile("ldmatrix.sync.aligned.m8n8.x4.shared.b16 {%0,%1,%2,%3}, [%4];" \
                 : "=r"((R)[0]), "=r"((R)[1]), "=r"((R)[2]), "=r"((R)[3]) : "r"(ADDR))

// ---------------------------------------------------------------------------
// Merged prep
// ---------------------------------------------------------------------------
#define WTN (2 * 3 * BDIM * BDIM)
#define WPREP_TOTAL (WTN + 2 * BDIM * BDIM + 2 * DFF * BDIM + NTOK * BDIM)
__global__ void wprep_kernel(const float* __restrict__ Wq, const float* __restrict__ Wk,
                             const float* __restrict__ Wv, const float* __restrict__ Wo,
                             const float* __restrict__ W1, const float* __restrict__ W2,
                             const float* __restrict__ src,
                             __half* __restrict__ wt, __half* __restrict__ wc,
                             __half* __restrict__ srch) {
    int e = blockIdx.x * 256 + threadIdx.x;
    if (e < WTN) {
        int m  = (e >= 3 * BDIM * BDIM);
        int e2 = e - m * 3 * BDIM * BDIM;
        int t  = e2 >> 18;
        int co = (e2 >> 9) & 511;
        int ci = e2 & 511;
        const float* s = m ? Wk : Wq;
        wt[e] = __float2half_rn(s[(size_t)co * 1536 + ci * 3 + t]);
        return;
    }
    int f = e - WTN;
    if (f < BDIM * BDIM)            { wc[WC_WV + f] = __float2half_rn(Wv[f]); return; }
    f -= BDIM * BDIM;
    if (f < BDIM * BDIM)            { wc[WC_WO + f] = __float2half_rn(Wo[f]); return; }
    f -= BDIM * BDIM;
    if (f < DFF * BDIM)             { wc[WC_W1 + f] = __float2half_rn(W1[f]); return; }
    f -= DFF * BDIM;
    if (f < DFF * BDIM)             { wc[WC_W2 + f] = __float2half_rn(W2[f]); return; }
    f -= DFF * BDIM;
    if (f < NTOK * BDIM)            { srch[f] = __float2half_rn(src[f]); return; }
}

// ===========================================================================
// gemm4: fp16 GEMM, 128(n) x 128(m) tile, 8 warps (32x64 each), KT=32,
// 2-stage cp.async ring. (R13-exact)
// ===========================================================================
#define G4_STRIDE 10240   // 128 rows * 80B

template <int MODE>
__global__ __launch_bounds__(256) void gemm4(const __half* __restrict__ A,
                                             const __half* __restrict__ W,
                                             const float* __restrict__ bias,
                                             const void* __restrict__ resv,
                                             void* __restrict__ outv, int M, int K) {
    __shared__ __align__(16) char Asm[2 * G4_STRIDE];
    __shared__ __align__(16) char Bsm[2 * G4_STRIDE];

    const int n0 = blockIdx.x * 128;
    const int m0 = blockIdx.y * 128;
    const int tid = threadIdx.x, lane = tid & 31, warp = tid >> 5;
    const int lq = lane >> 2, lr = lane & 3;
    const int nk = K >> 5;

    const uint32_t aBase = smem_u32(Asm);
    const uint32_t bBase = smem_u32(Bsm);

    const int crow = tid >> 2, cc = tid & 3;
    const __half* aSrc0 = A + (size_t)(n0 + crow) * K + cc * 8;
    const __half* aSrc1 = A + (size_t)(n0 + crow + 64) * K + cc * 8;
    const __half* bSrc0 = W + (size_t)(m0 + crow) * K + cc * 8;
    const __half* bSrc1 = W + (size_t)(m0 + crow + 64) * K + cc * 8;
    const uint32_t aDst0 = aBase + crow * 80 + cc * 16;
    const uint32_t aDst1 = aDst0 + 64 * 80;
    const uint32_t bDst0 = bBase + crow * 80 + cc * 16;
    const uint32_t bDst1 = bDst0 + 64 * 80;

    const int wiB = (warp >> 1) * 32;
    const int wjB = (warp & 1) * 64;
    const uint32_t aAddr0 = aBase + (wiB + (lane & 15)) * 80 + (lane >> 4) * 16;
    const uint32_t aAddr1 = aAddr0 + 16 * 80;
    const int bRowOff = (lane & 7) + ((lane >> 4) << 3);
    const int bColB   = ((lane >> 3) & 1) * 16;
    const uint32_t bAddr = bBase + (wjB + bRowOff) * 80 + bColB;

    float acc[2][8][4];
    #pragma unroll
    for (int mi = 0; mi < 2; mi++)
        #pragma unroll
        for (int ni = 0; ni < 8; ni++)
            #pragma unroll
            for (int c = 0; c < 4; c++) acc[mi][ni][c] = 0.f;

    #define G4_ISSUE(ST, KB)                                                          \
        { size_t o = (size_t)(KB) * 32;                                               \
          CP16(aDst0 + (ST) * G4_STRIDE, aSrc0 + o);                                  \
          CP16(aDst1 + (ST) * G4_STRIDE, aSrc1 + o);                                  \
          CP16(bDst0 + (ST) * G4_STRIDE, bSrc0 + o);                                  \
          CP16(bDst1 + (ST) * G4_STRIDE, bSrc1 + o); }

    G4_ISSUE(0, 0) CP_COMMIT();

    int st = 0;
    for (int kb = 0; kb < nk; kb++) {
        CP_WAIT0();
        __syncthreads();
        if (kb + 1 < nk) { G4_ISSUE(st ^ 1, kb + 1) CP_COMMIT(); }

        const uint32_t oS = st * G4_STRIDE;
        #pragma unroll
        for (int ks = 0; ks < 2; ks++) {
            uint32_t a0[4], a1[4];
            LDSM_X4(a0, aAddr0 + oS + ks * 32);
            LDSM_X4(a1, aAddr1 + oS + ks * 32);
            #pragma unroll
            for (int g = 0; g < 4; g++) {
                uint32_t bg[4];
                LDSM_X4(bg, bAddr + oS + g * 16 * 80 + ks * 32);
                mma_f16(acc[0][2 * g],     a0, bg + 0);
                mma_f16(acc[1][2 * g],     a1, bg + 0);
                mma_f16(acc[0][2 * g + 1], a0, bg + 2);
                mma_f16(acc[1][2 * g + 1], a1, bg + 2);
            }
        }
        st ^= 1;
    }
    #undef G4_ISSUE

    #pragma unroll
    for (int mi = 0; mi < 2; mi++) {
        #pragma unroll
        for (int ni = 0; ni < 8; ni++) {
            int col = m0 + wjB + ni * 8 + 2 * lr;
            float bv0 = bias[col], bv1 = bias[col + 1];
            #pragma unroll
            for (int h = 0; h < 2; h++) {
                int n = n0 + wiB + mi * 16 + lq + h * 8;
                float x0 = acc[mi][ni][2 * h] + bv0;
                float x1 = acc[mi][ni][2 * h + 1] + bv1;
                if (MODE == 1) { x0 = fmaxf(x0, 0.f); x1 = fmaxf(x1, 0.f); }
                if (MODE == 0) {
                    const float* res = (const float*)resv;
                    x0 += res[(size_t)n * M + col];
                    x1 += res[(size_t)n * M + col + 1];
                }
                if (MODE == 2) {
                    const __half* res = (const __half*)resv;
                    float2 rf = __half22float2(*(const __half2*)&res[(size_t)n * M + col]);
                    x0 += rf.x; x1 += rf.y;
                }
                if (MODE == 3) {
                    __half* out = (__half*)outv;
                    int b = n >> 10, s = n & 1023;
                    out[((size_t)(b * BDIM + col)) * SDIM + s]     = __float2half_rn(x0);
                    out[((size_t)(b * BDIM + col + 1)) * SDIM + s] = __float2half_rn(x1);
                } else if (MODE == 1) {
                    __half* out = (__half*)outv;
                    *(__half2*)&out[(size_t)n * M + col] = __floats2half2_rn(x0, x1);
                } else {
                    float* out = (float*)outv;
                    *(float2*)&out[(size_t)n * M + col] = make_float2(x0, x1);
                }
            }
        }
    }
}

// ===========================================================================
// convqk4: fused Q+K conv (R13-exact).
// ===========================================================================
__global__ __launch_bounds__(256) void convqk4(const __half* __restrict__ A,
                                               const __half* __restrict__ Wt,
                                               const float* __restrict__ bq,
                                               const float* __restrict__ bk,
                                               __half* __restrict__ qo,
                                               __half* __restrict__ ko) {
    __shared__ __align__(16) char Asm[2 * G4_STRIDE];
    __shared__ __align__(16) char Bsm[2 * G4_STRIDE];

    const int n0 = blockIdx.x * 128;
    const int c0 = blockIdx.y * 64;
    const int tid = threadIdx.x, lane = tid & 31, warp = tid >> 5;
    const int lq = lane >> 2, lr = lane & 3;
    const int NST = 48;

    const uint32_t aBase = smem_u32(Asm);
    const uint32_t bBase = smem_u32(Bsm);

    const int crow = tid >> 2, cc = tid & 3;
    const uint32_t aDst0 = aBase + crow * 80 + cc * 16;
    const uint32_t aDst1 = aDst0 + 64 * 80;
    const uint32_t bDst0 = bBase + crow * 80 + cc * 16;
    const uint32_t bDst1 = bDst0 + 64 * 80;

    const uint32_t aAddr = aBase + (warp * 16 + (lane & 15)) * 80 + (lane >> 4) * 16;
    const int bRowOff = (lane & 7) + ((lane >> 4) << 3);
    const int bColB   = ((lane >> 3) & 1) * 16;
    const uint32_t bAddr0 = bBase + bRowOff * 80 + bColB;
    const uint32_t bAddr1 = bBase + (64 + bRowOff) * 80 + bColB;

    float acc[2][8][4];
    #pragma unroll
    for (int m = 0; m < 2; m++)
        #pragma unroll
        for (int ni = 0; ni < 8; ni++)
            #pragma unroll
            for (int c = 0; c < 4; c++) acc[m][ni][c] = 0.f;

    #define CQ_ISSUE(ST, T)                                                           \
        { int t_ = (T);                                                               \
          int tap_ = t_ >> 4; size_t ko_ = (size_t)(t_ & 15) * 32;                    \
          int roff_ = tap_ - 1;                                                       \
          { int n = n0 + crow; int s = (n & 1023) + roff_;                            \
            uint32_t sz = ((unsigned)s < 1024u) ? 16u : 0u;                           \
            int sc = s < 0 ? 0 : (s > 1023 ? 1023 : s);                               \
            const __half* sp = A + ((size_t)(n & ~1023) + sc) * BDIM + ko_ + cc * 8;  \
            CP16Z(aDst0 + (ST) * G4_STRIDE, sp, sz); }                                \
          { int n = n0 + crow + 64; int s = (n & 1023) + roff_;                       \
            uint32_t sz = ((unsigned)s < 1024u) ? 16u : 0u;                           \
            int sc = s < 0 ? 0 : (s > 1023 ? 1023 : s);                               \
            const __half* sp = A + ((size_t)(n & ~1023) + sc) * BDIM + ko_ + cc * 8;  \
            CP16Z(aDst1 + (ST) * G4_STRIDE, sp, sz); }                                \
          { const __half* sp0 = Wt + ((size_t)(0 * 3 + tap_) * BDIM + c0 + crow) * BDIM + ko_ + cc * 8; \
            CP16(bDst0 + (ST) * G4_STRIDE, sp0);                                      \
            const __half* sp1 = Wt + ((size_t)(1 * 3 + tap_) * BDIM + c0 + crow) * BDIM + ko_ + cc * 8; \
            CP16(bDst1 + (ST) * G4_STRIDE, sp1); } }

    CQ_ISSUE(0, 0) CP_COMMIT();

    int st = 0;
    for (int t = 0; t < NST; t++) {
        CP_WAIT0();
        __syncthreads();
        if (t + 1 < NST) { CQ_ISSUE(st ^ 1, t + 1) CP_COMMIT(); }

        const uint32_t oS = st * G4_STRIDE;
        #pragma unroll
        for (int ks = 0; ks < 2; ks++) {
            uint32_t a[4];
            LDSM_X4(a, aAddr + oS + ks * 32);
            #pragma unroll
            for (int g = 0; g < 4; g++) {
                uint32_t b0[4], b1[4];
                LDSM_X4(b0, bAddr0 + oS + g * 16 * 80 + ks * 32);
                LDSM_X4(b1, bAddr1 + oS + g * 16 * 80 + ks * 32);
                mma_f16(acc[0][2 * g],     a, b0 + 0);
                mma_f16(acc[0][2 * g + 1], a, b0 + 2);
                mma_f16(acc[1][2 * g],     a, b1 + 0);
                mma_f16(acc[1][2 * g + 1], a, b1 + 2);
            }
        }
        st ^= 1;
    }
    #undef CQ_ISSUE

    #pragma unroll
    for (int m = 0; m < 2; m++) {
        __half* outp = m ? ko : qo;
        const float* bp = m ? bk : bq;
        const float scl = m ? 1.0f : 0.015625f;
        #pragma unroll
        for (int ni = 0; ni < 8; ni++) {
            int col = c0 + ni * 8 + 2 * lr;
            float bv0 = bp[col], bv1 = bp[col + 1];
            int hh = col >> 6, dd = col & 63;
            #pragma unroll
            for (int h = 0; h < 2; h++) {
                int n = n0 + warp * 16 + lq + h * 8;
                int b = n >> 10, s = n & 1023;
                __half2 o2 = __floats2half2_rn((acc[m][ni][2 * h] + bv0) * scl,
                                               (acc[m][ni][2 * h + 1] + bv1) * scl);
                *(__half2*)&outp[(((size_t)(b * NHEADS + hh)) * SDIM + s) * HD + dd] = o2;
            }
        }
    }
}

// ===========================================================================
// attn_mma3: fp16 flash attention, 128-query tile, 256 threads (8 warps x
// 16 rows). K/V tiles 64x64 double-buffered cp.async; P-in-register PV.
// ===========================================================================
#define AT_STRIDE 144
#define AT_TILE   (64 * AT_STRIDE)

__global__ __launch_bounds__(256) void attn_mma3(const __half* __restrict__ q,
                                                 const __half* __restrict__ k,
                                                 const __half* __restrict__ v,
                                                 __half* __restrict__ av) {
    __shared__ __align__(16) char Ksm[2 * AT_TILE];
    __shared__ __align__(16) char Vsm[2 * AT_TILE];

    const int s0 = blockIdx.x * 128;
    const int h  = blockIdx.y;
    const int b  = blockIdx.z;
    const __half* qb = q + (size_t)(b * NHEADS + h) * SDIM * HD;
    const __half* kb = k + (size_t)(b * NHEADS + h) * SDIM * HD;
    const __half* vb = v + (size_t)(b * NHEADS + h) * HD * SDIM;

    const int tid  = threadIdx.x;
    const int lane = tid & 31;
    const int warp = tid >> 5;
    const int lq = lane >> 2;
    const int lr = lane & 3;

    const uint32_t kBase = smem_u32(Ksm);
    const uint32_t vBase = smem_u32(Vsm);

    const int bRowOff = (lane & 7) + ((lane >> 4) << 3);
    const int bColB   = ((lane >> 3) & 1) * 16;
    const uint32_t kFrag = kBase + bRowOff * AT_STRIDE + bColB;
    const uint32_t vFrag = vBase + bRowOff * AT_STRIDE + bColB;

    // ---- Stage 128 Q rows across BOTH K buffers (contiguous 2*AT_TILE) ----
    #pragma unroll
    for (int r = 0; r < 4; r++) {
        int id = tid + 256 * r;      // 0..1023
        int row = id >> 3, c = id & 7;
        CP16(kBase + row * AT_STRIDE + c * 16, qb + (size_t)(s0 + row) * HD + c * 8);
    }
    CP_COMMIT();
    CP_WAIT0();
    __syncthreads();
    uint32_t qf[4][4];
    {
        const uint32_t qAddr = kBase + (warp * 16 + (lane & 15)) * AT_STRIDE + (lane >> 4) * 16;
        #pragma unroll
        for (int ks = 0; ks < 4; ks++)
            LDSM_X4(qf[ks], qAddr + ks * 32);
    }
    __syncthreads();

    #define AT_ISSUE(BUF, T0)                                                          \
        { _Pragma("unroll")                                                            \
          for (int r = 0; r < 2; r++) {                                                \
              int id = tid + 256 * r;                                                  \
              int row = id >> 3, c = id & 7;                                           \
              uint32_t d = row * AT_STRIDE + c * 16 + (BUF) * AT_TILE;                 \
              CP16(kBase + d, kb + (size_t)((T0) + row) * HD + c * 8);                 \
              CP16(vBase + d, vb + (size_t)row * SDIM + (T0) + c * 8); } }

    AT_ISSUE(0, 0)
    CP_COMMIT();

    float m0v = -1e30f, m1v = -1e30f, l0 = 0.f, l1 = 0.f;
    float o[8][4];
    #pragma unroll
    for (int ni = 0; ni < 8; ni++)
        #pragma unroll
        for (int c = 0; c < 4; c++) o[ni][c] = 0.f;

    for (int t = 0; t < 16; t++) {
        if (t + 1 < 16) AT_ISSUE((t + 1) & 1, (t + 1) * 64)
        CP_COMMIT();
        if (t + 1 < 16) CP_WAIT1(); else CP_WAIT0();
        __syncthreads();

        const uint32_t off = (t & 1) * AT_TILE;

        // QK scores: each warp 16 rows x 64 t
        float sc[8][4];
        #pragma unroll
        for (int ni = 0; ni < 8; ni++)
            #pragma unroll
            for (int c = 0; c < 4; c++) sc[ni][c] = 0.f;
        #pragma unroll
        for (int ks = 0; ks < 4; ks++) {
            #pragma unroll
            for (int g = 0; g < 4; g++) {
                uint32_t kf[4];
                LDSM_X4(kf, kFrag + off + g * 16 * AT_STRIDE + ks * 32);
                mma_f16(sc[2 * g],     qf[ks], kf + 0);
                mma_f16(sc[2 * g + 1], qf[ks], kf + 2);
            }
        }

        // Online softmax
        float rm0 = -1e30f, rm1 = -1e30f;
        #pragma unroll
        for (int ni = 0; ni < 8; ni++) {
            rm0 = fmaxf(rm0, fmaxf(sc[ni][0], sc[ni][1]));
            rm1 = fmaxf(rm1, fmaxf(sc[ni][2], sc[ni][3]));
        }
        rm0 = fmaxf(rm0, __shfl_xor_sync(0xffffffffu, rm0, 1));
        rm0 = fmaxf(rm0, __shfl_xor_sync(0xffffffffu, rm0, 2));
        rm1 = fmaxf(rm1, __shfl_xor_sync(0xffffffffu, rm1, 1));
        rm1 = fmaxf(rm1, __shfl_xor_sync(0xffffffffu, rm1, 2));
        float mn0 = fmaxf(m0v, rm0), mn1 = fmaxf(m1v, rm1);
        float cr0 = __expf(m0v - mn0), cr1 = __expf(m1v - mn1);
        float rs0 = 0.f, rs1 = 0.f;
        #pragma unroll
        for (int ni = 0; ni < 8; ni++) {
            sc[ni][0] = __expf(sc[ni][0] - mn0);
            sc[ni][1] = __expf(sc[ni][1] - mn0);
            sc[ni][2] = __expf(sc[ni][2] - mn1);
            sc[ni][3] = __expf(sc[ni][3] - mn1);
            rs0 += sc[ni][0] + sc[ni][1];
            rs1 += sc[ni][2] + sc[ni][3];
        }
        rs0 += __shfl_xor_sync(0xffffffffu, rs0, 1);
        rs0 += __shfl_xor_sync(0xffffffffu, rs0, 2);
        rs1 += __shfl_xor_sync(0xffffffffu, rs1, 1);
        rs1 += __shfl_xor_sync(0xffffffffu, rs1, 2);
        l0 = l0 * cr0 + rs0;
        l1 = l1 * cr1 + rs1;
        m0v = mn0; m1v = mn1;
        #pragma unroll
        for (int ni = 0; ni < 8; ni++) {
            o[ni][0] *= cr0; o[ni][1] *= cr0;
            o[ni][2] *= cr1; o[ni][3] *= cr1;
        }

        // PV with P straight from registers
        #pragma unroll
        for (int ks = 0; ks < 4; ks++) {
            uint32_t pa[4];
            pa[0] = f2h2(sc[2 * ks][0],     sc[2 * ks][1]);
            pa[1] = f2h2(sc[2 * ks][2],     sc[2 * ks][3]);
            pa[2] = f2h2(sc[2 * ks + 1][0], sc[2 * ks + 1][1]);
            pa[3] = f2h2(sc[2 * ks + 1][2], sc[2 * ks + 1][3]);
            #pragma unroll
            for (int g = 0; g < 4; g++) {
                uint32_t vf[4];
                LDSM_X4(vf, vFrag + off + g * 16 * AT_STRIDE + ks * 32);
                mma_f16(o[2 * g],     pa, vf + 0);
                mma_f16(o[2 * g + 1], pa, vf + 2);
            }
        }
        __syncthreads();
    }
    #undef AT_ISSUE

    float inv0 = 1.0f / l0, inv1 = 1.0f / l1;
    const int rbase = s0 + warp * 16;
    #pragma unroll
    for (int ni = 0; ni < 8; ni++) {
        int col = h * HD + ni * 8 + 2 * lr;
        __half2 a = __floats2half2_rn(o[ni][0] * inv0, o[ni][1] * inv0);
        __half2 c = __floats2half2_rn(o[ni][2] * inv1, o[ni][3] * inv1);
        *(__half2*)&av[(size_t)(b * SDIM + rbase + lq) * BDIM + col]     = a;
        *(__half2*)&av[(size_t)(b * SDIM + rbase + lq + 8) * BDIM + col] = c;
    }
}

// ---------------------------------------------------------------------------
// LayerNorm over last dim (512). f32 in; templated output type.
// ---------------------------------------------------------------------------
template <typename OutT>
__global__ void ln_kernel(const float* __restrict__ in, const float* __restrict__ g,
                          const float* __restrict__ beta, OutT* __restrict__ out) {
    const int row = blockIdx.x;
    const float* x = in + (size_t)row * BDIM;
    const int tid = threadIdx.x;
    const int wid = tid >> 5, lane = tid & 31;

    float v0 = x[tid], v1 = x[tid + 256];
    __shared__ float red[8];

    float s = v0 + v1;
    #pragma unroll
    for (int off = 16; off > 0; off >>= 1)
        s += __shfl_xor_sync(0xffffffffu, s, off);
    if (lane == 0) red[wid] = s;
    __syncthreads();
    float tot = 0.f;
    #pragma unroll
    for (int i = 0; i < 8; i++) tot += red[i];
    float mu = tot * (1.0f / 512.0f);
    __syncthreads();

    float d0 = v0 - mu, d1 = v1 - mu;
    float sq = d0 * d0 + d1 * d1;
    #pragma unroll
    for (int off = 16; off > 0; off >>= 1)
        sq += __shfl_xor_sync(0xffffffffu, sq, off);
    if (lane == 0) red[wid] = sq;
    __syncthreads();
    float tot2 = 0.f;
    #pragma unroll
    for (int i = 0; i < 8; i++) tot2 += red[i];
    float rstd = rsqrtf(tot2 * (1.0f / 512.0f) + 1e-5f);

    float y0 = d0 * rstd * g[tid]       + beta[tid];
    float y1 = d1 * rstd * g[tid + 256] + beta[tid + 256];
    out[(size_t)row * BDIM + tid]       = (OutT)y0;
    out[(size_t)row * BDIM + tid + 256] = (OutT)y1;
}

// ---------------------------------------------------------------------------
extern "C" void kernel_launch(void* const* d_in, const int* in_sizes, int n_in,
                              void* d_out, int out_size) {
    const float* src = (const float*)d_in[0];
    const float* Wq  = (const float*)d_in[1];
    const float* bq  = (const float*)d_in[2];
    const float* Wk  = (const float*)d_in[3];
    const float* bk  = (const float*)d_in[4];
    const float* Wv  = (const float*)d_in[5];
    const float* bv  = (const float*)d_in[6];
    const float* Wo  = (const float*)d_in[7];
    const float* bo  = (const float*)d_in[8];
    const float* W1  = (const float*)d_in[9];
    const float* b1  = (const float*)d_in[10];
    const float* W2  = (const float*)d_in[11];
    const float* b2  = (const float*)d_in[12];
    const float* g1  = (const float*)d_in[13];
    const float* be1 = (const float*)d_in[14];
    const float* g2  = (const float*)d_in[15];
    const float* be2 = (const float*)d_in[16];
    float* out = (float*)d_out;

    float *t1;
    __half *srch, *q, *k, *v, *av, *x1, *ff, *wt, *wc;
    cudaGetSymbolAddress((void**)&srch, g_srch);
    cudaGetSymbolAddress((void**)&q,  g_q);
    cudaGetSymbolAddress((void**)&k,  g_k);
    cudaGetSymbolAddress((void**)&v,  g_v);
    cudaGetSymbolAddress((void**)&av, g_av);
    cudaGetSymbolAddress((void**)&t1, g_t1);
    cudaGetSymbolAddress((void**)&x1, g_x1);
    cudaGetSymbolAddress((void**)&ff, g_ff);
    cudaGetSymbolAddress((void**)&wt, g_wt);
    cudaGetSymbolAddress((void**)&wc, g_wc);

    wprep_kernel<<<(WPREP_TOTAL + 255) / 256, 256>>>(Wq, Wk, Wv, Wo, W1, W2, src, wt, wc, srch);

    convqk4<<<dim3(NTOK / 128, BDIM / 64), 256>>>(srch, wt, bq, bk, q, k);
    gemm4<3><<<dim3(NTOK / 128, BDIM / 128), 256>>>(srch, wc + WC_WV, bv, nullptr, v, BDIM, BDIM);

    attn_mma3<<<dim3(SDIM / 128, NHEADS, BATCH), 256>>>(q, k, v, av);

    gemm4<0><<<dim3(NTOK / 128, BDIM / 128), 256>>>(av, wc + WC_WO, bo, src, t1, BDIM, BDIM);
    ln_kernel<__half><<<NTOK, 256>>>(t1, g1, be1, x1);

    gemm4<1><<<dim3(NTOK / 128, DFF / 128), 256>>>(x1, wc + WC_W1, b1, nullptr, ff, DFF, BDIM);
    gemm4<2><<<dim3(NTOK / 128, BDIM / 128), 256>>>(ff, wc + WC_W2, b2, x1, t1, BDIM, DFF);
    ln_kernel<float><<<NTOK, 256>>>(t1, g2, be2, out);
}

// round 15
// speedup vs baseline: 1.0593x; 1.0593x over previous
#include <cuda_runtime.h>
#include <cuda_fp16.h>
#include <math.h>
#include <stdint.h>

#define BDIM   512
#define SDIM   1024
#define BATCH  8
#define NHEADS 8
#define HD     64
#define DFF    2048
#define NTOK   (BATCH * SDIM)   // 8192

// Scratch
__device__ __half g_srch[NTOK * BDIM];
__device__ __half g_q [BATCH * BDIM * SDIM];   // [B,H,S,64], pre-scaled by 1/64
__device__ __half g_k [BATCH * BDIM * SDIM];   // [B,H,S,64]
__device__ __half g_v [BATCH * BDIM * SDIM];   // [B,D,S]
__device__ __half g_av[NTOK * BDIM];
__device__ float  g_t1[NTOK * BDIM];
__device__ __half g_x1[NTOK * BDIM];
__device__ __half g_ff[NTOK * DFF];
__device__ __half g_wt[2 * 3 * BDIM * BDIM];
__device__ __half g_wc[2 * BDIM * BDIM + 2 * DFF * BDIM];

#define WC_WV 0
#define WC_WO (BDIM * BDIM)
#define WC_W1 (2 * BDIM * BDIM)
#define WC_W2 (2 * BDIM * BDIM + DFF * BDIM)

__device__ __forceinline__ uint32_t f2h2(float lo, float hi) {
    __half2 h = __floats2half2_rn(lo, hi);
    return *reinterpret_cast<uint32_t*>(&h);
}

__device__ __forceinline__ void mma_f16(float c[4], const uint32_t a[4], const uint32_t b[2]) {
    asm volatile(
        "mma.sync.aligned.m16n8k16.row.col.f32.f16.f16.f32 "
        "{%0,%1,%2,%3}, {%4,%5,%6,%7}, {%8,%9}, {%0,%1,%2,%3};"
        : "+f"(c[0]), "+f"(c[1]), "+f"(c[2]), "+f"(c[3])
        : "r"(a[0]), "r"(a[1]), "r"(a[2]), "r"(a[3]), "r"(b[0]), "r"(b[1]));
}

__device__ __forceinline__ uint32_t smem_u32(const void* p) {
    uint32_t a;
    asm("{ .reg .u64 t; cvta.to.shared.u64 t, %1; cvt.u32.u64 %0, t; }" : "=r"(a) : "l"(p));
    return a;
}

#define CP16(dst, src) \
    asm volatile("cp.async.cg.shared.global [%0], [%1], 16;" :: "r"(dst), "l"(src))
#define CP16Z(dst, src, sz) \
    asm volatile("cp.async.cg.shared.global [%0], [%1], 16, %2;" :: "r"(dst), "l"(src), "r"(sz))
#define CP_COMMIT() asm volatile("cp.async.commit_group;")
#define CP_WAIT1()  asm volatile("cp.async.wait_group 1;")
#define CP_WAIT0()  asm volatile("cp.async.wait_group 0;")

#define LDSM_X4(R, ADDR) \
    asm volatile("ldmatrix.sync.aligned.m8n8.x4.shared.b16 {%0,%1,%2,%3}, [%4];" \
                 : "=r"((R)[0]), "=r"((R)[1]), "=r"((R)[2]), "=r"((R)[3]) : "r"(ADDR))

// ---------------------------------------------------------------------------
// Merged prep
// ---------------------------------------------------------------------------
#define WTN (2 * 3 * BDIM * BDIM)
#define WPREP_TOTAL (WTN + 2 * BDIM * BDIM + 2 * DFF * BDIM + NTOK * BDIM)
__global__ void wprep_kernel(const float* __restrict__ Wq, const float* __restrict__ Wk,
                             const float* __restrict__ Wv, const float* __restrict__ Wo,
                             const float* __restrict__ W1, const float* __restrict__ W2,
                             const float* __restrict__ src,
                             __half* __restrict__ wt, __half* __restrict__ wc,
                             __half* __restrict__ srch) {
    int e = blockIdx.x * 256 + threadIdx.x;
    if (e < WTN) {
        int m  = (e >= 3 * BDIM * BDIM);
        int e2 = e - m * 3 * BDIM * BDIM;
        int t  = e2 >> 18;
        int co = (e2 >> 9) & 511;
        int ci = e2 & 511;
        const float* s = m ? Wk : Wq;
        wt[e] = __float2half_rn(s[(size_t)co * 1536 + ci * 3 + t]);
        return;
    }
    int f = e - WTN;
    if (f < BDIM * BDIM)            { wc[WC_WV + f] = __float2half_rn(Wv[f]); return; }
    f -= BDIM * BDIM;
    if (f < BDIM * BDIM)            { wc[WC_WO + f] = __float2half_rn(Wo[f]); return; }
    f -= BDIM * BDIM;
    if (f < DFF * BDIM)             { wc[WC_W1 + f] = __float2half_rn(W1[f]); return; }
    f -= DFF * BDIM;
    if (f < DFF * BDIM)             { wc[WC_W2 + f] = __float2half_rn(W2[f]); return; }
    f -= DFF * BDIM;
    if (f < NTOK * BDIM)            { srch[f] = __float2half_rn(src[f]); return; }
}

// ===========================================================================
// gemm4: fp16 GEMM, 128(n) x 128(m) tile, 8 warps (32x64 each), KT=32,
// 2-stage cp.async ring. (R13-exact)
// ===========================================================================
#define G4_STRIDE 10240   // 128 rows * 80B

template <int MODE>
__global__ __launch_bounds__(256) void gemm4(const __half* __restrict__ A,
                                             const __half* __restrict__ W,
                                             const float* __restrict__ bias,
                                             const void* __restrict__ resv,
                                             void* __restrict__ outv, int M, int K) {
    __shared__ __align__(16) char Asm[2 * G4_STRIDE];
    __shared__ __align__(16) char Bsm[2 * G4_STRIDE];

    const int n0 = blockIdx.x * 128;
    const int m0 = blockIdx.y * 128;
    const int tid = threadIdx.x, lane = tid & 31, warp = tid >> 5;
    const int lq = lane >> 2, lr = lane & 3;
    const int nk = K >> 5;

    const uint32_t aBase = smem_u32(Asm);
    const uint32_t bBase = smem_u32(Bsm);

    const int crow = tid >> 2, cc = tid & 3;
    const __half* aSrc0 = A + (size_t)(n0 + crow) * K + cc * 8;
    const __half* aSrc1 = A + (size_t)(n0 + crow + 64) * K + cc * 8;
    const __half* bSrc0 = W + (size_t)(m0 + crow) * K + cc * 8;
    const __half* bSrc1 = W + (size_t)(m0 + crow + 64) * K + cc * 8;
    const uint32_t aDst0 = aBase + crow * 80 + cc * 16;
    const uint32_t aDst1 = aDst0 + 64 * 80;
    const uint32_t bDst0 = bBase + crow * 80 + cc * 16;
    const uint32_t bDst1 = bDst0 + 64 * 80;

    const int wiB = (warp >> 1) * 32;
    const int wjB = (warp & 1) * 64;
    const uint32_t aAddr0 = aBase + (wiB + (lane & 15)) * 80 + (lane >> 4) * 16;
    const uint32_t aAddr1 = aAddr0 + 16 * 80;
    const int bRowOff = (lane & 7) + ((lane >> 4) << 3);
    const int bColB   = ((lane >> 3) & 1) * 16;
    const uint32_t bAddr = bBase + (wjB + bRowOff) * 80 + bColB;

    float acc[2][8][4];
    #pragma unroll
    for (int mi = 0; mi < 2; mi++)
        #pragma unroll
        for (int ni = 0; ni < 8; ni++)
            #pragma unroll
            for (int c = 0; c < 4; c++) acc[mi][ni][c] = 0.f;

    #define G4_ISSUE(ST, KB)                                                          \
        { size_t o = (size_t)(KB) * 32;                                               \
          CP16(aDst0 + (ST) * G4_STRIDE, aSrc0 + o);                                  \
          CP16(aDst1 + (ST) * G4_STRIDE, aSrc1 + o);                                  \
          CP16(bDst0 + (ST) * G4_STRIDE, bSrc0 + o);                                  \
          CP16(bDst1 + (ST) * G4_STRIDE, bSrc1 + o); }

    G4_ISSUE(0, 0) CP_COMMIT();

    int st = 0;
    for (int kb = 0; kb < nk; kb++) {
        CP_WAIT0();
        __syncthreads();
        if (kb + 1 < nk) { G4_ISSUE(st ^ 1, kb + 1) CP_COMMIT(); }

        const uint32_t oS = st * G4_STRIDE;
        #pragma unroll
        for (int ks = 0; ks < 2; ks++) {
            uint32_t a0[4], a1[4];
            LDSM_X4(a0, aAddr0 + oS + ks * 32);
            LDSM_X4(a1, aAddr1 + oS + ks * 32);
            #pragma unroll
            for (int g = 0; g < 4; g++) {
                uint32_t bg[4];
                LDSM_X4(bg, bAddr + oS + g * 16 * 80 + ks * 32);
                mma_f16(acc[0][2 * g],     a0, bg + 0);
                mma_f16(acc[1][2 * g],     a1, bg + 0);
                mma_f16(acc[0][2 * g + 1], a0, bg + 2);
                mma_f16(acc[1][2 * g + 1], a1, bg + 2);
            }
        }
        st ^= 1;
    }
    #undef G4_ISSUE

    #pragma unroll
    for (int mi = 0; mi < 2; mi++) {
        #pragma unroll
        for (int ni = 0; ni < 8; ni++) {
            int col = m0 + wjB + ni * 8 + 2 * lr;
            float bv0 = bias[col], bv1 = bias[col + 1];
            #pragma unroll
            for (int h = 0; h < 2; h++) {
                int n = n0 + wiB + mi * 16 + lq + h * 8;
                float x0 = acc[mi][ni][2 * h] + bv0;
                float x1 = acc[mi][ni][2 * h + 1] + bv1;
                if (MODE == 1) { x0 = fmaxf(x0, 0.f); x1 = fmaxf(x1, 0.f); }
                if (MODE == 0) {
                    const float* res = (const float*)resv;
                    x0 += res[(size_t)n * M + col];
                    x1 += res[(size_t)n * M + col + 1];
                }
                if (MODE == 2) {
                    const __half* res = (const __half*)resv;
                    float2 rf = __half22float2(*(const __half2*)&res[(size_t)n * M + col]);
                    x0 += rf.x; x1 += rf.y;
                }
                if (MODE == 3) {
                    __half* out = (__half*)outv;
                    int b = n >> 10, s = n & 1023;
                    out[((size_t)(b * BDIM + col)) * SDIM + s]     = __float2half_rn(x0);
                    out[((size_t)(b * BDIM + col + 1)) * SDIM + s] = __float2half_rn(x1);
                } else if (MODE == 1) {
                    __half* out = (__half*)outv;
                    *(__half2*)&out[(size_t)n * M + col] = __floats2half2_rn(x0, x1);
                } else {
                    float* out = (float*)outv;
                    *(float2*)&out[(size_t)n * M + col] = make_float2(x0, x1);
                }
            }
        }
    }
}

// ===========================================================================
// convqk5: fused Q+K conv with HALO A tile. Block 128(tok) x 64(co) x 2 mats.
// 16 stages (one per 32-k chunk); per stage: A staged once with +/-1 halo
// (130 rows), all 3 taps computed via ldmatrix row-offset; B staged for all
// 3 taps (2 mats x 64 co each). Dynamic smem, 2-stage ring.
// ===========================================================================
#define CQ5_ASTR  10560            // 132 rows * 80B (rows 0..129 used)
#define CQ5_BOFF  CQ5_ASTR
#define CQ5_BTAP  10240            // 128 rows * 80B per tap
#define CQ5_STAGE (CQ5_ASTR + 3 * CQ5_BTAP)   // 41280
#define CQ5_SMEM  (2 * CQ5_STAGE)             // 82560

__global__ __launch_bounds__(256) void convqk5(const __half* __restrict__ A,
                                               const __half* __restrict__ Wt,
                                               const float* __restrict__ bq,
                                               const float* __restrict__ bk,
                                               __half* __restrict__ qo,
                                               __half* __restrict__ ko) {
    extern __shared__ __align__(16) char dsm[];
    const uint32_t base = smem_u32(dsm);

    const int n0 = blockIdx.x * 128;
    const int c0 = blockIdx.y * 64;
    const int tid = threadIdx.x, lane = tid & 31, warp = tid >> 5;
    const int lq = lane >> 2, lr = lane & 3;

    const int sBase = n0 & 1023;                       // 128-token block within one sequence
    const __half* Ab = A + (size_t)(n0 & ~1023) * BDIM;

    // Fragment addressing
    const uint32_t aAddr = base + (warp * 16 + (lane & 15)) * 80 + (lane >> 4) * 16;
    const int bRowOff = (lane & 7) + ((lane >> 4) << 3);
    const int bColB   = ((lane >> 3) & 1) * 16;
    const uint32_t bAddr0 = base + CQ5_BOFF + bRowOff * 80 + bColB;           // mat0
    const uint32_t bAddr1 = bAddr0 + 64 * 80;                                 // mat1

    float acc[2][8][4];
    #pragma unroll
    for (int m = 0; m < 2; m++)
        #pragma unroll
        for (int ni = 0; ni < 8; ni++)
            #pragma unroll
            for (int c = 0; c < 4; c++) acc[m][ni][c] = 0.f;

    // Issue one stage: A halo tile (130 rows x 32 halves) + B (3 taps x 128 rows)
    #define CQ5_ISSUE(ST, KB)                                                         \
        { size_t ko_ = (size_t)(KB) * 32;                                             \
          uint32_t sb = base + (ST) * CQ5_STAGE;                                      \
          _Pragma("unroll")                                                           \
          for (int r = 0; r < 3; r++) {                                               \
              int id = tid + 256 * r;                                                 \
              if (id < 520) {                                                         \
                  int row = id >> 2, c = id & 3;                                      \
                  int s = sBase + row - 1;                                            \
                  uint32_t sz = ((unsigned)s < 1024u) ? 16u : 0u;                     \
                  int sc = s < 0 ? 0 : (s > 1023 ? 1023 : s);                         \
                  CP16Z(sb + row * 80 + c * 16,                                       \
                        Ab + (size_t)sc * BDIM + ko_ + c * 8, sz);                    \
              } }                                                                     \
          _Pragma("unroll")                                                           \
          for (int r = 0; r < 6; r++) {                                               \
              int id = tid + 256 * r;                                                 \
              int tap = id >> 9, rem = id & 511;                                      \
              int row = rem >> 2, c = rem & 3;                                        \
              int mat = row >> 6, co = c0 + (row & 63);                               \
              CP16(sb + CQ5_BOFF + tap * CQ5_BTAP + row * 80 + c * 16,                \
                   Wt + ((size_t)(mat * 3 + tap) * BDIM + co) * BDIM + ko_ + c * 8);  \
          } }

    CQ5_ISSUE(0, 0) CP_COMMIT();

    int st = 0;
    for (int kb = 0; kb < 16; kb++) {
        CP_WAIT0();
        __syncthreads();
        if (kb + 1 < 16) { CQ5_ISSUE(st ^ 1, kb + 1) CP_COMMIT(); }

        const uint32_t oS = st * CQ5_STAGE;
        #pragma unroll
        for (int ks = 0; ks < 2; ks++) {
            #pragma unroll
            for (int tap = 0; tap < 3; tap++) {
                uint32_t a[4];
                // A rows shifted by tap (smem row = local_row + tap; tap-1 = conv offset)
                LDSM_X4(a, aAddr + oS + tap * 80 + ks * 32);
                const uint32_t bo = oS + tap * CQ5_BTAP + ks * 32;
                #pragma unroll
                for (int g = 0; g < 4; g++) {
                    uint32_t b0[4], b1[4];
                    LDSM_X4(b0, bAddr0 + bo + g * 16 * 80);
                    LDSM_X4(b1, bAddr1 + bo + g * 16 * 80);
                    mma_f16(acc[0][2 * g],     a, b0 + 0);
                    mma_f16(acc[0][2 * g + 1], a, b0 + 2);
                    mma_f16(acc[1][2 * g],     a, b1 + 0);
                    mma_f16(acc[1][2 * g + 1], a, b1 + 2);
                }
            }
        }
        st ^= 1;
    }
    #undef CQ5_ISSUE

    #pragma unroll
    for (int m = 0; m < 2; m++) {
        __half* outp = m ? ko : qo;
        const float* bp = m ? bk : bq;
        const float scl = m ? 1.0f : 0.015625f;   // fold 1/64 into Q
        #pragma unroll
        for (int ni = 0; ni < 8; ni++) {
            int col = c0 + ni * 8 + 2 * lr;
            float bv0 = bp[col], bv1 = bp[col + 1];
            int hh = col >> 6, dd = col & 63;
            #pragma unroll
            for (int h = 0; h < 2; h++) {
                int n = n0 + warp * 16 + lq + h * 8;
                int b = n >> 10, s = n & 1023;
                __half2 o2 = __floats2half2_rn((acc[m][ni][2 * h] + bv0) * scl,
                                               (acc[m][ni][2 * h + 1] + bv1) * scl);
                *(__half2*)&outp[(((size_t)(b * NHEADS + hh)) * SDIM + s) * HD + dd] = o2;
            }
        }
    }
}

// ===========================================================================
// attn_mma2: fp16 flash attention (R12-exact: 64-query tile, 128 threads).
// ===========================================================================
#define AT_STRIDE 144
#define AT_TILE   (64 * AT_STRIDE)

__global__ __launch_bounds__(128) void attn_mma2(const __half* __restrict__ q,
                                                 const __half* __restrict__ k,
                                                 const __half* __restrict__ v,
                                                 __half* __restrict__ av) {
    __shared__ __align__(16) char Ksm[2 * AT_TILE];
    __shared__ __align__(16) char Vsm[2 * AT_TILE];

    const int s0 = blockIdx.x * 64;
    const int h  = blockIdx.y;
    const int b  = blockIdx.z;
    const __half* qb = q + (size_t)(b * NHEADS + h) * SDIM * HD;
    const __half* kb = k + (size_t)(b * NHEADS + h) * SDIM * HD;
    const __half* vb = v + (size_t)(b * NHEADS + h) * HD * SDIM;

    const int tid  = threadIdx.x;
    const int lane = tid & 31;
    const int warp = tid >> 5;
    const int lq = lane >> 2;
    const int lr = lane & 3;

    const uint32_t kBase = smem_u32(Ksm);
    const uint32_t vBase = smem_u32(Vsm);

    const int bRowOff = (lane & 7) + ((lane >> 4) << 3);
    const int bColB   = ((lane >> 3) & 1) * 16;
    const uint32_t kFrag = kBase + bRowOff * AT_STRIDE + bColB;
    const uint32_t vFrag = vBase + bRowOff * AT_STRIDE + bColB;

    #pragma unroll
    for (int r = 0; r < 4; r++) {
        int id = tid + 128 * r;
        int row = id >> 3, c = id & 7;
        CP16(kBase + row * AT_STRIDE + c * 16, qb + (size_t)(s0 + row) * HD + c * 8);
    }
    CP_COMMIT();
    CP_WAIT0();
    __syncthreads();
    uint32_t qf[4][4];
    {
        const uint32_t qAddr = kBase + (warp * 16 + (lane & 15)) * AT_STRIDE + (lane >> 4) * 16;
        #pragma unroll
        for (int ks = 0; ks < 4; ks++)
            LDSM_X4(qf[ks], qAddr + ks * 32);
    }
    __syncthreads();

    #define AT_ISSUE(BUF, T0)                                                          \
        { _Pragma("unroll")                                                            \
          for (int r = 0; r < 4; r++) {                                                \
              int id = tid + 128 * r;                                                  \
              int row = id >> 3, c = id & 7;                                           \
              uint32_t d = row * AT_STRIDE + c * 16 + (BUF) * AT_TILE;                 \
              CP16(kBase + d, kb + (size_t)((T0) + row) * HD + c * 8);                 \
              CP16(vBase + d, vb + (size_t)row * SDIM + (T0) + c * 8); } }

    AT_ISSUE(0, 0)
    CP_COMMIT();

    float m0v = -1e30f, m1v = -1e30f, l0 = 0.f, l1 = 0.f;
    float o[8][4];
    #pragma unroll
    for (int ni = 0; ni < 8; ni++)
        #pragma unroll
        for (int c = 0; c < 4; c++) o[ni][c] = 0.f;

    for (int t = 0; t < 16; t++) {
        if (t + 1 < 16) AT_ISSUE((t + 1) & 1, (t + 1) * 64)
        CP_COMMIT();
        if (t + 1 < 16) CP_WAIT1(); else CP_WAIT0();
        __syncthreads();

        const uint32_t off = (t & 1) * AT_TILE;

        float sc[8][4];
        #pragma unroll
        for (int ni = 0; ni < 8; ni++)
            #pragma unroll
            for (int c = 0; c < 4; c++) sc[ni][c] = 0.f;
        #pragma unroll
        for (int ks = 0; ks < 4; ks++) {
            #pragma unroll
            for (int g = 0; g < 4; g++) {
                uint32_t kf[4];
                LDSM_X4(kf, kFrag + off + g * 16 * AT_STRIDE + ks * 32);
                mma_f16(sc[2 * g],     qf[ks], kf + 0);
                mma_f16(sc[2 * g + 1], qf[ks], kf + 2);
            }
        }

        float rm0 = -1e30f, rm1 = -1e30f;
        #pragma unroll
        for (int ni = 0; ni < 8; ni++) {
            rm0 = fmaxf(rm0, fmaxf(sc[ni][0], sc[ni][1]));
            rm1 = fmaxf(rm1, fmaxf(sc[ni][2], sc[ni][3]));
        }
        rm0 = fmaxf(rm0, __shfl_xor_sync(0xffffffffu, rm0, 1));
        rm0 = fmaxf(rm0, __shfl_xor_sync(0xffffffffu, rm0, 2));
        rm1 = fmaxf(rm1, __shfl_xor_sync(0xffffffffu, rm1, 1));
        rm1 = fmaxf(rm1, __shfl_xor_sync(0xffffffffu, rm1, 2));
        float mn0 = fmaxf(m0v, rm0), mn1 = fmaxf(m1v, rm1);
        float cr0 = __expf(m0v - mn0), cr1 = __expf(m1v - mn1);
        float rs0 = 0.f, rs1 = 0.f;
        #pragma unroll
        for (int ni = 0; ni < 8; ni++) {
            sc[ni][0] = __expf(sc[ni][0] - mn0);
            sc[ni][1] = __expf(sc[ni][1] - mn0);
            sc[ni][2] = __expf(sc[ni][2] - mn1);
            sc[ni][3] = __expf(sc[ni][3] - mn1);
            rs0 += sc[ni][0] + sc[ni][1];
            rs1 += sc[ni][2] + sc[ni][3];
        }
        rs0 += __shfl_xor_sync(0xffffffffu, rs0, 1);
        rs0 += __shfl_xor_sync(0xffffffffu, rs0, 2);
        rs1 += __shfl_xor_sync(0xffffffffu, rs1, 1);
        rs1 += __shfl_xor_sync(0xffffffffu, rs1, 2);
        l0 = l0 * cr0 + rs0;
        l1 = l1 * cr1 + rs1;
        m0v = mn0; m1v = mn1;
        #pragma unroll
        for (int ni = 0; ni < 8; ni++) {
            o[ni][0] *= cr0; o[ni][1] *= cr0;
            o[ni][2] *= cr1; o[ni][3] *= cr1;
        }

        #pragma unroll
        for (int ks = 0; ks < 4; ks++) {
            uint32_t pa[4];
            pa[0] = f2h2(sc[2 * ks][0],     sc[2 * ks][1]);
            pa[1] = f2h2(sc[2 * ks][2],     sc[2 * ks][3]);
            pa[2] = f2h2(sc[2 * ks + 1][0], sc[2 * ks + 1][1]);
            pa[3] = f2h2(sc[2 * ks + 1][2], sc[2 * ks + 1][3]);
            #pragma unroll
            for (int g = 0; g < 4; g++) {
                uint32_t vf[4];
                LDSM_X4(vf, vFrag + off + g * 16 * AT_STRIDE + ks * 32);
                mma_f16(o[2 * g],     pa, vf + 0);
                mma_f16(o[2 * g + 1], pa, vf + 2);
            }
        }
        __syncthreads();
    }
    #undef AT_ISSUE

    float inv0 = 1.0f / l0, inv1 = 1.0f / l1;
    const int rbase = s0 + warp * 16;
    #pragma unroll
    for (int ni = 0; ni < 8; ni++) {
        int col = h * HD + ni * 8 + 2 * lr;
        __half2 a = __floats2half2_rn(o[ni][0] * inv0, o[ni][1] * inv0);
        __half2 c = __floats2half2_rn(o[ni][2] * inv1, o[ni][3] * inv1);
        *(__half2*)&av[(size_t)(b * SDIM + rbase + lq) * BDIM + col]     = a;
        *(__half2*)&av[(size_t)(b * SDIM + rbase + lq + 8) * BDIM + col] = c;
    }
}

// ---------------------------------------------------------------------------
// LayerNorm over last dim (512). f32 in; templated output type.
// ---------------------------------------------------------------------------
template <typename OutT>
__global__ void ln_kernel(const float* __restrict__ in, const float* __restrict__ g,
                          const float* __restrict__ beta, OutT* __restrict__ out) {
    const int row = blockIdx.x;
    const float* x = in + (size_t)row * BDIM;
    const int tid = threadIdx.x;
    const int wid = tid >> 5, lane = tid & 31;

    float v0 = x[tid], v1 = x[tid + 256];
    __shared__ float red[8];

    float s = v0 + v1;
    #pragma unroll
    for (int off = 16; off > 0; off >>= 1)
        s += __shfl_xor_sync(0xffffffffu, s, off);
    if (lane == 0) red[wid] = s;
    __syncthreads();
    float tot = 0.f;
    #pragma unroll
    for (int i = 0; i < 8; i++) tot += red[i];
    float mu = tot * (1.0f / 512.0f);
    __syncthreads();

    float d0 = v0 - mu, d1 = v1 - mu;
    float sq = d0 * d0 + d1 * d1;
    #pragma unroll
    for (int off = 16; off > 0; off >>= 1)
        sq += __shfl_xor_sync(0xffffffffu, sq, off);
    if (lane == 0) red[wid] = sq;
    __syncthreads();
    float tot2 = 0.f;
    #pragma unroll
    for (int i = 0; i < 8; i++) tot2 += red[i];
    float rstd = rsqrtf(tot2 * (1.0f / 512.0f) + 1e-5f);

    float y0 = d0 * rstd * g[tid]       + beta[tid];
    float y1 = d1 * rstd * g[tid + 256] + beta[tid + 256];
    out[(size_t)row * BDIM + tid]       = (OutT)y0;
    out[(size_t)row * BDIM + tid + 256] = (OutT)y1;
}

// ---------------------------------------------------------------------------
extern "C" void kernel_launch(void* const* d_in, const int* in_sizes, int n_in,
                              void* d_out, int out_size) {
    const float* src = (const float*)d_in[0];
    const float* Wq  = (const float*)d_in[1];
    const float* bq  = (const float*)d_in[2];
    const float* Wk  = (const float*)d_in[3];
    const float* bk  = (const float*)d_in[4];
    const float* Wv  = (const float*)d_in[5];
    const float* bv  = (const float*)d_in[6];
    const float* Wo  = (const float*)d_in[7];
    const float* bo  = (const float*)d_in[8];
    const float* W1  = (const float*)d_in[9];
    const float* b1  = (const float*)d_in[10];
    const float* W2  = (const float*)d_in[11];
    const float* b2  = (const float*)d_in[12];
    const float* g1  = (const float*)d_in[13];
    const float* be1 = (const float*)d_in[14];
    const float* g2  = (const float*)d_in[15];
    const float* be2 = (const float*)d_in[16];
    float* out = (float*)d_out;

    float *t1;
    __half *srch, *q, *k, *v, *av, *x1, *ff, *wt, *wc;
    cudaGetSymbolAddress((void**)&srch, g_srch);
    cudaGetSymbolAddress((void**)&q,  g_q);
    cudaGetSymbolAddress((void**)&k,  g_k);
    cudaGetSymbolAddress((void**)&v,  g_v);
    cudaGetSymbolAddress((void**)&av, g_av);
    cudaGetSymbolAddress((void**)&t1, g_t1);
    cudaGetSymbolAddress((void**)&x1, g_x1);
    cudaGetSymbolAddress((void**)&ff, g_ff);
    cudaGetSymbolAddress((void**)&wt, g_wt);
    cudaGetSymbolAddress((void**)&wc, g_wc);

    cudaFuncSetAttribute(convqk5, cudaFuncAttributeMaxDynamicSharedMemorySize, CQ5_SMEM);

    wprep_kernel<<<(WPREP_TOTAL + 255) / 256, 256>>>(Wq, Wk, Wv, Wo, W1, W2, src, wt, wc, srch);

    convqk5<<<dim3(NTOK / 128, BDIM / 64), 256, CQ5_SMEM>>>(srch, wt, bq, bk, q, k);
    gemm4<3><<<dim3(NTOK / 128, BDIM / 128), 256>>>(srch, wc + WC_WV, bv, nullptr, v, BDIM, BDIM);

    attn_mma2<<<dim3(SDIM / 64, NHEADS, BATCH), 128>>>(q, k, v, av);

    gemm4<0><<<dim3(NTOK / 128, BDIM / 128), 256>>>(av, wc + WC_WO, bo, src, t1, BDIM, BDIM);
    ln_kernel<__half><<<NTOK, 256>>>(t1, g1, be1, x1);

    gemm4<1><<<dim3(NTOK / 128, DFF / 128), 256>>>(x1, wc + WC_W1, b1, nullptr, ff, DFF, BDIM);
    gemm4<2><<<dim3(NTOK / 128, BDIM / 128), 256>>>(ff, wc + WC_W2, b2, x1, t1, BDIM, DFF);
    ln_kernel<float><<<NTOK, 256>>>(t1, g2, be2, out);
}

// round 16
// speedup vs baseline: 1.0769x; 1.0166x over previous
#include <cuda_runtime.h>
#include <cuda_fp16.h>
#include <math.h>
#include <stdint.h>

#define BDIM   512
#define SDIM   1024
#define BATCH  8
#define NHEADS 8
#define HD     64
#define DFF    2048
#define NTOK   (BATCH * SDIM)   // 8192

// Scratch
__device__ __half g_srch[NTOK * BDIM];
__device__ __half g_q [BATCH * BDIM * SDIM];   // [B,H,S,64], pre-scaled by log2e/64
__device__ __half g_k [BATCH * BDIM * SDIM];   // [B,H,S,64]
__device__ __half g_v [BATCH * BDIM * SDIM];   // [B,D,S]
__device__ __half g_av[NTOK * BDIM];
__device__ float  g_t1[NTOK * BDIM];
__device__ __half g_x1[NTOK * BDIM];
__device__ __half g_ff[NTOK * DFF];
__device__ __half g_wt[2 * 3 * BDIM * BDIM];
__device__ __half g_wc[2 * BDIM * BDIM + 2 * DFF * BDIM];

#define WC_WV 0
#define WC_WO (BDIM * BDIM)
#define WC_W1 (2 * BDIM * BDIM)
#define WC_W2 (2 * BDIM * BDIM + DFF * BDIM)

__device__ __forceinline__ uint32_t f2h2(float lo, float hi) {
    __half2 h = __floats2half2_rn(lo, hi);
    return *reinterpret_cast<uint32_t*>(&h);
}

__device__ __forceinline__ float ex2(float x) {
    float r;
    asm("ex2.approx.ftz.f32 %0, %1;" : "=f"(r) : "f"(x));
    return r;
}

__device__ __forceinline__ void mma_f16(float c[4], const uint32_t a[4], const uint32_t b[2]) {
    asm volatile(
        "mma.sync.aligned.m16n8k16.row.col.f32.f16.f16.f32 "
        "{%0,%1,%2,%3}, {%4,%5,%6,%7}, {%8,%9}, {%0,%1,%2,%3};"
        : "+f"(c[0]), "+f"(c[1]), "+f"(c[2]), "+f"(c[3])
        : "r"(a[0]), "r"(a[1]), "r"(a[2]), "r"(a[3]), "r"(b[0]), "r"(b[1]));
}

__device__ __forceinline__ uint32_t smem_u32(const void* p) {
    uint32_t a;
    asm("{ .reg .u64 t; cvta.to.shared.u64 t, %1; cvt.u32.u64 %0, t; }" : "=r"(a) : "l"(p));
    return a;
}

#define CP16(dst, src) \
    asm volatile("cp.async.cg.shared.global [%0], [%1], 16;" :: "r"(dst), "l"(src))
#define CP16Z(dst, src, sz) \
    asm volatile("cp.async.cg.shared.global [%0], [%1], 16, %2;" :: "r"(dst), "l"(src), "r"(sz))
#define CP_COMMIT() asm volatile("cp.async.commit_group;")
#define CP_WAIT1()  asm volatile("cp.async.wait_group 1;")
#define CP_WAIT0()  asm volatile("cp.async.wait_group 0;")

#define LDSM_X4(R, ADDR) \
    asm volatile("ldmatrix.sync.aligned.m8n8.x4.shared.b16 {%0,%1,%2,%3}, [%4];" \
                 : "=r"((R)[0]), "=r"((R)[1]), "=r"((R)[2]), "=r"((R)[3]) : "r"(ADDR))

// ---------------------------------------------------------------------------
// Merged prep
// ---------------------------------------------------------------------------
#define WTN (2 * 3 * BDIM * BDIM)
#define WPREP_TOTAL (WTN + 2 * BDIM * BDIM + 2 * DFF * BDIM + NTOK * BDIM)
__global__ void wprep_kernel(const float* __restrict__ Wq, const float* __restrict__ Wk,
                             const float* __restrict__ Wv, const float* __restrict__ Wo,
                             const float* __restrict__ W1, const float* __restrict__ W2,
                             const float* __restrict__ src,
                             __half* __restrict__ wt, __half* __restrict__ wc,
                             __half* __restrict__ srch) {
    int e = blockIdx.x * 256 + threadIdx.x;
    if (e < WTN) {
        int m  = (e >= 3 * BDIM * BDIM);
        int e2 = e - m * 3 * BDIM * BDIM;
        int t  = e2 >> 18;
        int co = (e2 >> 9) & 511;
        int ci = e2 & 511;
        const float* s = m ? Wk : Wq;
        wt[e] = __float2half_rn(s[(size_t)co * 1536 + ci * 3 + t]);
        return;
    }
    int f = e - WTN;
    if (f < BDIM * BDIM)            { wc[WC_WV + f] = __float2half_rn(Wv[f]); return; }
    f -= BDIM * BDIM;
    if (f < BDIM * BDIM)            { wc[WC_WO + f] = __float2half_rn(Wo[f]); return; }
    f -= BDIM * BDIM;
    if (f < DFF * BDIM)             { wc[WC_W1 + f] = __float2half_rn(W1[f]); return; }
    f -= DFF * BDIM;
    if (f < DFF * BDIM)             { wc[WC_W2 + f] = __float2half_rn(W2[f]); return; }
    f -= DFF * BDIM;
    if (f < NTOK * BDIM)            { srch[f] = __float2half_rn(src[f]); return; }
}

// ===========================================================================
// gemm4: fp16 GEMM, 128(n) x 128(m) tile, 8 warps (32x64 each), KT=32,
// 2-stage cp.async ring. (R13-exact)
// ===========================================================================
#define G4_STRIDE 10240   // 128 rows * 80B

template <int MODE>
__global__ __launch_bounds__(256) void gemm4(const __half* __restrict__ A,
                                             const __half* __restrict__ W,
                                             const float* __restrict__ bias,
                                             const void* __restrict__ resv,
                                             void* __restrict__ outv, int M, int K) {
    __shared__ __align__(16) char Asm[2 * G4_STRIDE];
    __shared__ __align__(16) char Bsm[2 * G4_STRIDE];

    const int n0 = blockIdx.x * 128;
    const int m0 = blockIdx.y * 128;
    const int tid = threadIdx.x, lane = tid & 31, warp = tid >> 5;
    const int lq = lane >> 2, lr = lane & 3;
    const int nk = K >> 5;

    const uint32_t aBase = smem_u32(Asm);
    const uint32_t bBase = smem_u32(Bsm);

    const int crow = tid >> 2, cc = tid & 3;
    const __half* aSrc0 = A + (size_t)(n0 + crow) * K + cc * 8;
    const __half* aSrc1 = A + (size_t)(n0 + crow + 64) * K + cc * 8;
    const __half* bSrc0 = W + (size_t)(m0 + crow) * K + cc * 8;
    const __half* bSrc1 = W + (size_t)(m0 + crow + 64) * K + cc * 8;
    const uint32_t aDst0 = aBase + crow * 80 + cc * 16;
    const uint32_t aDst1 = aDst0 + 64 * 80;
    const uint32_t bDst0 = bBase + crow * 80 + cc * 16;
    const uint32_t bDst1 = bDst0 + 64 * 80;

    const int wiB = (warp >> 1) * 32;
    const int wjB = (warp & 1) * 64;
    const uint32_t aAddr0 = aBase + (wiB + (lane & 15)) * 80 + (lane >> 4) * 16;
    const uint32_t aAddr1 = aAddr0 + 16 * 80;
    const int bRowOff = (lane & 7) + ((lane >> 4) << 3);
    const int bColB   = ((lane >> 3) & 1) * 16;
    const uint32_t bAddr = bBase + (wjB + bRowOff) * 80 + bColB;

    float acc[2][8][4];
    #pragma unroll
    for (int mi = 0; mi < 2; mi++)
        #pragma unroll
        for (int ni = 0; ni < 8; ni++)
            #pragma unroll
            for (int c = 0; c < 4; c++) acc[mi][ni][c] = 0.f;

    #define G4_ISSUE(ST, KB)                                                          \
        { size_t o = (size_t)(KB) * 32;                                               \
          CP16(aDst0 + (ST) * G4_STRIDE, aSrc0 + o);                                  \
          CP16(aDst1 + (ST) * G4_STRIDE, aSrc1 + o);                                  \
          CP16(bDst0 + (ST) * G4_STRIDE, bSrc0 + o);                                  \
          CP16(bDst1 + (ST) * G4_STRIDE, bSrc1 + o); }

    G4_ISSUE(0, 0) CP_COMMIT();

    int st = 0;
    for (int kb = 0; kb < nk; kb++) {
        CP_WAIT0();
        __syncthreads();
        if (kb + 1 < nk) { G4_ISSUE(st ^ 1, kb + 1) CP_COMMIT(); }

        const uint32_t oS = st * G4_STRIDE;
        #pragma unroll
        for (int ks = 0; ks < 2; ks++) {
            uint32_t a0[4], a1[4];
            LDSM_X4(a0, aAddr0 + oS + ks * 32);
            LDSM_X4(a1, aAddr1 + oS + ks * 32);
            #pragma unroll
            for (int g = 0; g < 4; g++) {
                uint32_t bg[4];
                LDSM_X4(bg, bAddr + oS + g * 16 * 80 + ks * 32);
                mma_f16(acc[0][2 * g],     a0, bg + 0);
                mma_f16(acc[1][2 * g],     a1, bg + 0);
                mma_f16(acc[0][2 * g + 1], a0, bg + 2);
                mma_f16(acc[1][2 * g + 1], a1, bg + 2);
            }
        }
        st ^= 1;
    }
    #undef G4_ISSUE

    #pragma unroll
    for (int mi = 0; mi < 2; mi++) {
        #pragma unroll
        for (int ni = 0; ni < 8; ni++) {
            int col = m0 + wjB + ni * 8 + 2 * lr;
            float bv0 = bias[col], bv1 = bias[col + 1];
            #pragma unroll
            for (int h = 0; h < 2; h++) {
                int n = n0 + wiB + mi * 16 + lq + h * 8;
                float x0 = acc[mi][ni][2 * h] + bv0;
                float x1 = acc[mi][ni][2 * h + 1] + bv1;
                if (MODE == 1) { x0 = fmaxf(x0, 0.f); x1 = fmaxf(x1, 0.f); }
                if (MODE == 0) {
                    const float* res = (const float*)resv;
                    x0 += res[(size_t)n * M + col];
                    x1 += res[(size_t)n * M + col + 1];
                }
                if (MODE == 2) {
                    const __half* res = (const __half*)resv;
                    float2 rf = __half22float2(*(const __half2*)&res[(size_t)n * M + col]);
                    x0 += rf.x; x1 += rf.y;
                }
                if (MODE == 3) {
                    __half* out = (__half*)outv;
                    int b = n >> 10, s = n & 1023;
                    out[((size_t)(b * BDIM + col)) * SDIM + s]     = __float2half_rn(x0);
                    out[((size_t)(b * BDIM + col + 1)) * SDIM + s] = __float2half_rn(x1);
                } else if (MODE == 1) {
                    __half* out = (__half*)outv;
                    *(__half2*)&out[(size_t)n * M + col] = __floats2half2_rn(x0, x1);
                } else {
                    float* out = (float*)outv;
                    *(float2*)&out[(size_t)n * M + col] = make_float2(x0, x1);
                }
            }
        }
    }
}

// ===========================================================================
// convqk5: fused Q+K conv with HALO A tile (R15-exact except Q scale folds
// log2e for the exp2-domain softmax).
// ===========================================================================
#define CQ5_ASTR  10560
#define CQ5_BOFF  CQ5_ASTR
#define CQ5_BTAP  10240
#define CQ5_STAGE (CQ5_ASTR + 3 * CQ5_BTAP)
#define CQ5_SMEM  (2 * CQ5_STAGE)

__global__ __launch_bounds__(256) void convqk5(const __half* __restrict__ A,
                                               const __half* __restrict__ Wt,
                                               const float* __restrict__ bq,
                                               const float* __restrict__ bk,
                                               __half* __restrict__ qo,
                                               __half* __restrict__ ko) {
    extern __shared__ __align__(16) char dsm[];
    const uint32_t base = smem_u32(dsm);

    const int n0 = blockIdx.x * 128;
    const int c0 = blockIdx.y * 64;
    const int tid = threadIdx.x, lane = tid & 31, warp = tid >> 5;
    const int lq = lane >> 2, lr = lane & 3;

    const int sBase = n0 & 1023;
    const __half* Ab = A + (size_t)(n0 & ~1023) * BDIM;

    const uint32_t aAddr = base + (warp * 16 + (lane & 15)) * 80 + (lane >> 4) * 16;
    const int bRowOff = (lane & 7) + ((lane >> 4) << 3);
    const int bColB   = ((lane >> 3) & 1) * 16;
    const uint32_t bAddr0 = base + CQ5_BOFF + bRowOff * 80 + bColB;
    const uint32_t bAddr1 = bAddr0 + 64 * 80;

    float acc[2][8][4];
    #pragma unroll
    for (int m = 0; m < 2; m++)
        #pragma unroll
        for (int ni = 0; ni < 8; ni++)
            #pragma unroll
            for (int c = 0; c < 4; c++) acc[m][ni][c] = 0.f;

    #define CQ5_ISSUE(ST, KB)                                                         \
        { size_t ko_ = (size_t)(KB) * 32;                                             \
          uint32_t sb = base + (ST) * CQ5_STAGE;                                      \
          _Pragma("unroll")                                                           \
          for (int r = 0; r < 3; r++) {                                               \
              int id = tid + 256 * r;                                                 \
              if (id < 520) {                                                         \
                  int row = id >> 2, c = id & 3;                                      \
                  int s = sBase + row - 1;                                            \
                  uint32_t sz = ((unsigned)s < 1024u) ? 16u : 0u;                     \
                  int sc = s < 0 ? 0 : (s > 1023 ? 1023 : s);                         \
                  CP16Z(sb + row * 80 + c * 16,                                       \
                        Ab + (size_t)sc * BDIM + ko_ + c * 8, sz);                    \
              } }                                                                     \
          _Pragma("unroll")                                                           \
          for (int r = 0; r < 6; r++) {                                               \
              int id = tid + 256 * r;                                                 \
              int tap = id >> 9, rem = id & 511;                                      \
              int row = rem >> 2, c = rem & 3;                                        \
              int mat = row >> 6, co = c0 + (row & 63);                               \
              CP16(sb + CQ5_BOFF + tap * CQ5_BTAP + row * 80 + c * 16,                \
                   Wt + ((size_t)(mat * 3 + tap) * BDIM + co) * BDIM + ko_ + c * 8);  \
          } }

    CQ5_ISSUE(0, 0) CP_COMMIT();

    int st = 0;
    for (int kb = 0; kb < 16; kb++) {
        CP_WAIT0();
        __syncthreads();
        if (kb + 1 < 16) { CQ5_ISSUE(st ^ 1, kb + 1) CP_COMMIT(); }

        const uint32_t oS = st * CQ5_STAGE;
        #pragma unroll
        for (int ks = 0; ks < 2; ks++) {
            #pragma unroll
            for (int tap = 0; tap < 3; tap++) {
                uint32_t a[4];
                LDSM_X4(a, aAddr + oS + tap * 80 + ks * 32);
                const uint32_t bo = oS + tap * CQ5_BTAP + ks * 32;
                #pragma unroll
                for (int g = 0; g < 4; g++) {
                    uint32_t b0[4], b1[4];
                    LDSM_X4(b0, bAddr0 + bo + g * 16 * 80);
                    LDSM_X4(b1, bAddr1 + bo + g * 16 * 80);
                    mma_f16(acc[0][2 * g],     a, b0 + 0);
                    mma_f16(acc[0][2 * g + 1], a, b0 + 2);
                    mma_f16(acc[1][2 * g],     a, b1 + 0);
                    mma_f16(acc[1][2 * g + 1], a, b1 + 2);
                }
            }
        }
        st ^= 1;
    }
    #undef CQ5_ISSUE

    #pragma unroll
    for (int m = 0; m < 2; m++) {
        __half* outp = m ? ko : qo;
        const float* bp = m ? bk : bq;
        // Q scaled by log2(e)/64 (exp2-domain softmax); K unscaled
        const float scl = m ? 1.0f : (1.4426950408889634f / 64.0f);
        #pragma unroll
        for (int ni = 0; ni < 8; ni++) {
            int col = c0 + ni * 8 + 2 * lr;
            float bv0 = bp[col], bv1 = bp[col + 1];
            int hh = col >> 6, dd = col & 63;
            #pragma unroll
            for (int h = 0; h < 2; h++) {
                int n = n0 + warp * 16 + lq + h * 8;
                int b = n >> 10, s = n & 1023;
                __half2 o2 = __floats2half2_rn((acc[m][ni][2 * h] + bv0) * scl,
                                               (acc[m][ni][2 * h + 1] + bv1) * scl);
                *(__half2*)&outp[(((size_t)(b * NHEADS + hh)) * SDIM + s) * HD + dd] = o2;
            }
        }
    }
}

// ===========================================================================
// attn_mma4: fp16 flash attention, 64-query tile, 128 threads,
// 3-buffer cp.async ring (ONE barrier/tile), exp2-domain softmax,
// deferred l-reduction (no sum shuffles in the loop). Dynamic smem 54KB.
// ===========================================================================
#define AT_STRIDE 144
#define AT_TILE   (64 * AT_STRIDE)   // 9216B
#define AT_SMEM   (6 * AT_TILE)      // 3 K bufs + 3 V bufs = 55296B

__global__ __launch_bounds__(128) void attn_mma4(const __half* __restrict__ q,
                                                 const __half* __restrict__ k,
                                                 const __half* __restrict__ v,
                                                 __half* __restrict__ av) {
    extern __shared__ __align__(16) char dsm[];

    const int s0 = blockIdx.x * 64;
    const int h  = blockIdx.y;
    const int b  = blockIdx.z;
    const __half* qb = q + (size_t)(b * NHEADS + h) * SDIM * HD;
    const __half* kb = k + (size_t)(b * NHEADS + h) * SDIM * HD;
    const __half* vb = v + (size_t)(b * NHEADS + h) * HD * SDIM;

    const int tid  = threadIdx.x;
    const int lane = tid & 31;
    const int warp = tid >> 5;
    const int lq = lane >> 2;
    const int lr = lane & 3;

    const uint32_t kBase = smem_u32(dsm);
    const uint32_t vBase = kBase + 3 * AT_TILE;

    const int bRowOff = (lane & 7) + ((lane >> 4) << 3);
    const int bColB   = ((lane >> 3) & 1) * 16;
    const uint32_t kFrag = kBase + bRowOff * AT_STRIDE + bColB;
    const uint32_t vFrag = vBase + bRowOff * AT_STRIDE + bColB;

    // ---- Q fragments via cp.async stage into K buf0 ----
    #pragma unroll
    for (int r = 0; r < 4; r++) {
        int id = tid + 128 * r;
        int row = id >> 3, c = id & 7;
        CP16(kBase + row * AT_STRIDE + c * 16, qb + (size_t)(s0 + row) * HD + c * 8);
    }
    CP_COMMIT();
    CP_WAIT0();
    __syncthreads();
    uint32_t qf[4][4];
    {
        const uint32_t qAddr = kBase + (warp * 16 + (lane & 15)) * AT_STRIDE + (lane >> 4) * 16;
        #pragma unroll
        for (int ks = 0; ks < 4; ks++)
            LDSM_X4(qf[ks], qAddr + ks * 32);
    }
    __syncthreads();

    #define AT_ISSUE(BUF, T0)                                                          \
        { _Pragma("unroll")                                                            \
          for (int r = 0; r < 4; r++) {                                                \
              int id = tid + 128 * r;                                                  \
              int row = id >> 3, c = id & 7;                                           \
              uint32_t d = row * AT_STRIDE + c * 16 + (BUF) * AT_TILE;                 \
              CP16(kBase + d, kb + (size_t)((T0) + row) * HD + c * 8);                 \
              CP16(vBase + d, vb + (size_t)row * SDIM + (T0) + c * 8); } }

    AT_ISSUE(0, 0)   CP_COMMIT();
    AT_ISSUE(1, 64)  CP_COMMIT();

    float m0v = -1e30f, m1v = -1e30f, l0 = 0.f, l1 = 0.f;   // l: per-lane partials
    float o[8][4];
    #pragma unroll
    for (int ni = 0; ni < 8; ni++)
        #pragma unroll
        for (int c = 0; c < 4; c++) o[ni][c] = 0.f;

    for (int t = 0; t < 16; t++) {
        if (t + 1 < 16) CP_WAIT1(); else CP_WAIT0();
        __syncthreads();                    // single barrier per tile
        if (t + 2 < 16) AT_ISSUE((t + 2) % 3, (t + 2) * 64)
        CP_COMMIT();

        const uint32_t off = (t % 3) * AT_TILE;

        // QK scores (log2 domain)
        float sc[8][4];
        #pragma unroll
        for (int ni = 0; ni < 8; ni++)
            #pragma unroll
            for (int c = 0; c < 4; c++) sc[ni][c] = 0.f;
        #pragma unroll
        for (int ks = 0; ks < 4; ks++) {
            #pragma unroll
            for (int g = 0; g < 4; g++) {
                uint32_t kf[4];
                LDSM_X4(kf, kFrag + off + g * 16 * AT_STRIDE + ks * 32);
                mma_f16(sc[2 * g],     qf[ks], kf + 0);
                mma_f16(sc[2 * g + 1], qf[ks], kf + 2);
            }
        }

        // Online softmax: max via shfl; sums stay lane-local
        float rm0 = -1e30f, rm1 = -1e30f;
        #pragma unroll
        for (int ni = 0; ni < 8; ni++) {
            rm0 = fmaxf(rm0, fmaxf(sc[ni][0], sc[ni][1]));
            rm1 = fmaxf(rm1, fmaxf(sc[ni][2], sc[ni][3]));
        }
        rm0 = fmaxf(rm0, __shfl_xor_sync(0xffffffffu, rm0, 1));
        rm0 = fmaxf(rm0, __shfl_xor_sync(0xffffffffu, rm0, 2));
        rm1 = fmaxf(rm1, __shfl_xor_sync(0xffffffffu, rm1, 1));
        rm1 = fmaxf(rm1, __shfl_xor_sync(0xffffffffu, rm1, 2));
        float mn0 = fmaxf(m0v, rm0), mn1 = fmaxf(m1v, rm1);
        float cr0 = ex2(m0v - mn0), cr1 = ex2(m1v - mn1);
        float rs0 = 0.f, rs1 = 0.f;
        #pragma unroll
        for (int ni = 0; ni < 8; ni++) {
            sc[ni][0] = ex2(sc[ni][0] - mn0);
            sc[ni][1] = ex2(sc[ni][1] - mn0);
            sc[ni][2] = ex2(sc[ni][2] - mn1);
            sc[ni][3] = ex2(sc[ni][3] - mn1);
            rs0 += sc[ni][0] + sc[ni][1];
            rs1 += sc[ni][2] + sc[ni][3];
        }
        l0 = l0 * cr0 + rs0;
        l1 = l1 * cr1 + rs1;
        m0v = mn0; m1v = mn1;
        #pragma unroll
        for (int ni = 0; ni < 8; ni++) {
            o[ni][0] *= cr0; o[ni][1] *= cr0;
            o[ni][2] *= cr1; o[ni][3] *= cr1;
        }

        // PV: P fragments straight from registers
        #pragma unroll
        for (int ks = 0; ks < 4; ks++) {
            uint32_t pa[4];
            pa[0] = f2h2(sc[2 * ks][0],     sc[2 * ks][1]);
            pa[1] = f2h2(sc[2 * ks][2],     sc[2 * ks][3]);
            pa[2] = f2h2(sc[2 * ks + 1][0], sc[2 * ks + 1][1]);
            pa[3] = f2h2(sc[2 * ks + 1][2], sc[2 * ks + 1][3]);
            #pragma unroll
            for (int g = 0; g < 4; g++) {
                uint32_t vf[4];
                LDSM_X4(vf, vFrag + off + g * 16 * AT_STRIDE + ks * 32);
                mma_f16(o[2 * g],     pa, vf + 0);
                mma_f16(o[2 * g + 1], pa, vf + 2);
            }
        }
        // no trailing barrier: buffer (t%3) is next written at iteration t+1,
        // whose leading __syncthreads orders it after all reads here.
    }
    #undef AT_ISSUE

    // Final l reduction across the quad
    l0 += __shfl_xor_sync(0xffffffffu, l0, 1);
    l0 += __shfl_xor_sync(0xffffffffu, l0, 2);
    l1 += __shfl_xor_sync(0xffffffffu, l1, 1);
    l1 += __shfl_xor_sync(0xffffffffu, l1, 2);

    float inv0 = 1.0f / l0, inv1 = 1.0f / l1;
    const int rbase = s0 + warp * 16;
    #pragma unroll
    for (int ni = 0; ni < 8; ni++) {
        int col = h * HD + ni * 8 + 2 * lr;
        __half2 a = __floats2half2_rn(o[ni][0] * inv0, o[ni][1] * inv0);
        __half2 c = __floats2half2_rn(o[ni][2] * inv1, o[ni][3] * inv1);
        *(__half2*)&av[(size_t)(b * SDIM + rbase + lq) * BDIM + col]     = a;
        *(__half2*)&av[(size_t)(b * SDIM + rbase + lq + 8) * BDIM + col] = c;
    }
}

// ---------------------------------------------------------------------------
// LayerNorm over last dim (512). f32 in; templated output type.
// ---------------------------------------------------------------------------
template <typename OutT>
__global__ void ln_kernel(const float* __restrict__ in, const float* __restrict__ g,
                          const float* __restrict__ beta, OutT* __restrict__ out) {
    const int row = blockIdx.x;
    const float* x = in + (size_t)row * BDIM;
    const int tid = threadIdx.x;
    const int wid = tid >> 5, lane = tid & 31;

    float v0 = x[tid], v1 = x[tid + 256];
    __shared__ float red[8];

    float s = v0 + v1;
    #pragma unroll
    for (int off = 16; off > 0; off >>= 1)
        s += __shfl_xor_sync(0xffffffffu, s, off);
    if (lane == 0) red[wid] = s;
    __syncthreads();
    float tot = 0.f;
    #pragma unroll
    for (int i = 0; i < 8; i++) tot += red[i];
    float mu = tot * (1.0f / 512.0f);
    __syncthreads();

    float d0 = v0 - mu, d1 = v1 - mu;
    float sq = d0 * d0 + d1 * d1;
    #pragma unroll
    for (int off = 16; off > 0; off >>= 1)
        sq += __shfl_xor_sync(0xffffffffu, sq, off);
    if (lane == 0) red[wid] = sq;
    __syncthreads();
    float tot2 = 0.f;
    #pragma unroll
    for (int i = 0; i < 8; i++) tot2 += red[i];
    float rstd = rsqrtf(tot2 * (1.0f / 512.0f) + 1e-5f);

    float y0 = d0 * rstd * g[tid]       + beta[tid];
    float y1 = d1 * rstd * g[tid + 256] + beta[tid + 256];
    out[(size_t)row * BDIM + tid]       = (OutT)y0;
    out[(size_t)row * BDIM + tid + 256] = (OutT)y1;
}

// ---------------------------------------------------------------------------
extern "C" void kernel_launch(void* const* d_in, const int* in_sizes, int n_in,
                              void* d_out, int out_size) {
    const float* src = (const float*)d_in[0];
    const float* Wq  = (const float*)d_in[1];
    const float* bq  = (const float*)d_in[2];
    const float* Wk  = (const float*)d_in[3];
    const float* bk  = (const float*)d_in[4];
    const float* Wv  = (const float*)d_in[5];
    const float* bv  = (const float*)d_in[6];
    const float* Wo  = (const float*)d_in[7];
    const float* bo  = (const float*)d_in[8];
    const float* W1  = (const float*)d_in[9];
    const float* b1  = (const float*)d_in[10];
    const float* W2  = (const float*)d_in[11];
    const float* b2  = (const float*)d_in[12];
    const float* g1  = (const float*)d_in[13];
    const float* be1 = (const float*)d_in[14];
    const float* g2  = (const float*)d_in[15];
    const float* be2 = (const float*)d_in[16];
    float* out = (float*)d_out;

    float *t1;
    __half *srch, *q, *k, *v, *av, *x1, *ff, *wt, *wc;
    cudaGetSymbolAddress((void**)&srch, g_srch);
    cudaGetSymbolAddress((void**)&q,  g_q);
    cudaGetSymbolAddress((void**)&k,  g_k);
    cudaGetSymbolAddress((void**)&v,  g_v);
    cudaGetSymbolAddress((void**)&av, g_av);
    cudaGetSymbolAddress((void**)&t1, g_t1);
    cudaGetSymbolAddress((void**)&x1, g_x1);
    cudaGetSymbolAddress((void**)&ff, g_ff);
    cudaGetSymbolAddress((void**)&wt, g_wt);
    cudaGetSymbolAddress((void**)&wc, g_wc);

    cudaFuncSetAttribute(convqk5, cudaFuncAttributeMaxDynamicSharedMemorySize, CQ5_SMEM);
    cudaFuncSetAttribute(attn_mma4, cudaFuncAttributeMaxDynamicSharedMemorySize, AT_SMEM);

    wprep_kernel<<<(WPREP_TOTAL + 255) / 256, 256>>>(Wq, Wk, Wv, Wo, W1, W2, src, wt, wc, srch);

    convqk5<<<dim3(NTOK / 128, BDIM / 64), 256, CQ5_SMEM>>>(srch, wt, bq, bk, q, k);
    gemm4<3><<<dim3(NTOK / 128, BDIM / 128), 256>>>(srch, wc + WC_WV, bv, nullptr, v, BDIM, BDIM);

    attn_mma4<<<dim3(SDIM / 64, NHEADS, BATCH), 128, AT_SMEM>>>(q, k, v, av);

    gemm4<0><<<dim3(NTOK / 128, BDIM / 128), 256>>>(av, wc + WC_WO, bo, src, t1, BDIM, BDIM);
    ln_kernel<__half><<<NTOK, 256>>>(t1, g1, be1, x1);

    gemm4<1><<<dim3(NTOK / 128, DFF / 128), 256>>>(x1, wc + WC_W1, b1, nullptr, ff, DFF, BDIM);
    gemm4<2><<<dim3(NTOK / 128, BDIM / 128), 256>>>(ff, wc + WC_W2, b2, x1, t1, BDIM, DFF);
    ln_kernel<float><<<NTOK, 256>>>(t1, g2, be2, out);
}